// round 7
// baseline (speedup 1.0000x reference)
#include <cuda_runtime.h>
#include <cuda_fp16.h>
#include <cstdint>
#include <math.h>

#define B_DIM 8
#define S_DIM 2048
#define H_DIM 512
#define NROWS (B_DIM * S_DIM)          // 16384
#define NSTACK (3 * H_DIM)             // 1536

// ---------------- scratch (device globals; no allocations allowed) ----------
__device__ float g_pe[S_DIM * H_DIM];
__device__ float g_bias[NSTACK];
__device__ __half g_xh[NROWS * H_DIM], g_xl[NROWS * H_DIM];
__device__ __half g_wh[NSTACK * H_DIM], g_wl[NSTACK * H_DIM];   // stacked Wq,Wk,Wv
__device__ __half g_qh[NROWS * H_DIM], g_ql[NROWS * H_DIM];
__device__ __half g_kh[NROWS * H_DIM], g_kl[NROWS * H_DIM];
__device__ __half g_vt[H_DIM * NROWS];                          // v transposed, single fp16
__device__ float g_sc[(long long)B_DIM * S_DIM * S_DIM];        // 134 MB
__device__ __half g_ph[(long long)B_DIM * S_DIM * S_DIM];       // probs fp16

// ---------------- helpers ----------------------------------------------
__device__ __forceinline__ uint32_t smem_u32(const void* p) {
    uint32_t a;
    asm("{ .reg .u64 t; cvta.to.shared.u64 t, %1; cvt.u32.u64 %0, t; }" : "=r"(a) : "l"(p));
    return a;
}
__device__ __forceinline__ void cp16(uint32_t dst, const void* src) {
    asm volatile("cp.async.cg.shared.global [%0], [%1], 16;"
                 :: "r"(dst), "l"(__cvta_generic_to_global(src)));
}
#define CP_COMMIT() asm volatile("cp.async.commit_group;" ::: "memory")
#define CP_WAIT_1() asm volatile("cp.async.wait_group 1;" ::: "memory")
#define CP_WAIT_0() asm volatile("cp.async.wait_group 0;" ::: "memory")

__device__ __forceinline__ void ldsm4(uint32_t& r0, uint32_t& r1, uint32_t& r2, uint32_t& r3,
                                      uint32_t addr) {
    asm volatile("ldmatrix.sync.aligned.m8n8.x4.shared.b16 {%0,%1,%2,%3}, [%4];"
                 : "=r"(r0), "=r"(r1), "=r"(r2), "=r"(r3) : "r"(addr));
}
__device__ __forceinline__ void mma16816(float* c, const uint32_t* a, const uint32_t* b) {
    asm volatile(
        "mma.sync.aligned.m16n8k16.row.col.f32.f16.f16.f32 "
        "{%0,%1,%2,%3}, {%4,%5,%6,%7}, {%8,%9}, {%0,%1,%2,%3};"
        : "+f"(c[0]), "+f"(c[1]), "+f"(c[2]), "+f"(c[3])
        : "r"(a[0]), "r"(a[1]), "r"(a[2]), "r"(a[3]), "r"(b[0]), "r"(b[1]));
}
__device__ __forceinline__ void split2h(float v, unsigned short& h, unsigned short& l) {
    __half hh = __float2half_rn(v);
    __half ll = __float2half_rn(v - __half2float(hh));
    h = __half_as_ushort(hh);
    l = __half_as_ushort(ll);
}

// ---------------- split-fp16 HMMA GEMM: C = A * B^T -------------------------
// Block tile 128(M) x 256(N), BK=32, 512 threads (4x4 warps), warp tile 32x64.
// SMEM rows: pitch 80B (64B data + 16B pad) -> conflict-free ldsm.
// NPROD=3: A hi/lo + B hi/lo (3-product). NPROD=1: single x single.
struct GemmParams {
    const __half *Ah, *Al, *Bh, *Bl;
    const float* bias;                  // stacked bias for MODE 0
    long long aBatch, bBatch;
    int aRow, bRow, K;
    __half *qh, *ql, *kh, *kl, *vt;    // MODE 0 outputs
    float* outF;                        // MODE 2 output
    long long oBatch;
    int oRow;
};

#define PITCH   80
#define TILE_A  (128 * PITCH)           // 10240
#define TILE_B  (256 * PITCH)           // 20480
#define A_UNITS 512                     // 128 rows x 4 16B-chunks
#define B_UNITS 1024                    // 256 rows x 4 16B-chunks

template<int NPROD, int MODE>   // MODE: 0 = fused QKV epilogue, 2 = fp32 out
__global__ __launch_bounds__(512, 1) void tc_gemm(GemmParams p) {
    constexpr int STAGE = (NPROD == 3) ? (2 * TILE_A + 2 * TILE_B) : (TILE_A + TILE_B);
    extern __shared__ char smem[];
    uint32_t sbase = smem_u32(smem);

    const int tid = threadIdx.x;
    const int wid = tid >> 5, lane = tid & 31;
    const int wm = wid & 3, wn = wid >> 2;          // 4x4 warps: (wm*32, wn*64)

    const int bm = blockIdx.y * 128, bn = blockIdx.x * 256, z = blockIdx.z;
    const __half* Ah = p.Ah + (long long)z * p.aBatch;
    const __half* Al = p.Al + (long long)z * p.aBatch;
    const __half* Bh = p.Bh + (long long)z * p.bBatch;
    const __half* Bl = p.Bl + (long long)z * p.bBatch;
    const int aRow = p.aRow, bRow = p.bRow;

    const int nc = p.K >> 5;

    auto load_chunk = [&](int c, int s) {
        uint32_t st = sbase + s * STAGE;
        long long kofs = (long long)c * 32;
#pragma unroll
        for (int t = 0; t < ((NPROD == 3) ? 2 : 1); t++) {
            const __half* src = t ? Al : Ah;
            uint32_t tb = st + t * TILE_A;
            {   // A_UNITS == 512 == blockDim: exactly one unit per thread
                int row = tid >> 2, ch = tid & 3;
                cp16(tb + row * PITCH + ch * 16,
                     src + (long long)(bm + row) * aRow + kofs + ch * 8);
            }
        }
        uint32_t bb = st + ((NPROD == 3) ? 2 * TILE_A : TILE_A);
#pragma unroll
        for (int t = 0; t < ((NPROD == 3) ? 2 : 1); t++) {
            const __half* src = t ? Bl : Bh;
            uint32_t tb = bb + t * TILE_B;
#pragma unroll
            for (int it = 0; it < 2; it++) {
                int u = tid + it * 512;            // B_UNITS == 1024
                int row = u >> 2, ch = u & 3;
                cp16(tb + row * PITCH + ch * 16,
                     src + (long long)(bn + row) * bRow + kofs + ch * 8);
            }
        }
        CP_COMMIT();
    };

    float acc[2][8][4];
#pragma unroll
    for (int i = 0; i < 2; i++)
#pragma unroll
        for (int j = 0; j < 8; j++)
#pragma unroll
            for (int r = 0; r < 4; r++) acc[i][j][r] = 0.f;

    load_chunk(0, 0);
    if (nc > 1) load_chunk(1, 1);

    for (int c = 0; c < nc; c++) {
        int s = c & 1;
        if (c == nc - 1) CP_WAIT_0(); else CP_WAIT_1();
        __syncthreads();

        uint32_t st = sbase + s * STAGE;
        uint32_t aHB = st, aLB = st + TILE_A;
        uint32_t bHB = st + ((NPROD == 3) ? 2 * TILE_A : TILE_A);
        uint32_t bLB = bHB + TILE_B;

#pragma unroll
        for (int ks = 0; ks < 2; ks++) {
            const int chcol = (ks * 2 + (lane >> 4)) * 16;
            uint32_t ah[2][4], al[2][4];
#pragma unroll
            for (int t = 0; t < 2; t++) {
                int row = wm * 32 + t * 16 + (lane & 15);
                uint32_t off = row * PITCH + chcol;
                ldsm4(ah[t][0], ah[t][1], ah[t][2], ah[t][3], aHB + off);
                if (NPROD == 3)
                    ldsm4(al[t][0], al[t][1], al[t][2], al[t][3], aLB + off);
            }
#pragma unroll
            for (int jh = 0; jh < 2; jh++) {
                uint32_t bh[4][2], bl[4][2];
#pragma unroll
                for (int jj = 0; jj < 2; jj++) {
                    int row = wn * 64 + (jh * 2 + jj) * 16 + (lane & 15);
                    uint32_t off = row * PITCH + chcol;
                    uint32_t r0, r1, r2, r3;
                    ldsm4(r0, r1, r2, r3, bHB + off);
                    bh[jj * 2][0] = r0; bh[jj * 2][1] = r2;
                    bh[jj * 2 + 1][0] = r1; bh[jj * 2 + 1][1] = r3;
                    if (NPROD == 3) {
                        ldsm4(r0, r1, r2, r3, bLB + off);
                        bl[jj * 2][0] = r0; bl[jj * 2][1] = r2;
                        bl[jj * 2 + 1][0] = r1; bl[jj * 2 + 1][1] = r3;
                    }
                }
#pragma unroll
                for (int i = 0; i < 2; i++)
#pragma unroll
                    for (int j4 = 0; j4 < 4; j4++)
                        mma16816(acc[i][jh * 4 + j4], ah[i], bh[j4]);
                if (NPROD == 3) {
#pragma unroll
                    for (int i = 0; i < 2; i++)
#pragma unroll
                        for (int j4 = 0; j4 < 4; j4++)
                            mma16816(acc[i][jh * 4 + j4], ah[i], bl[j4]);
#pragma unroll
                    for (int i = 0; i < 2; i++)
#pragma unroll
                        for (int j4 = 0; j4 < 4; j4++)
                            mma16816(acc[i][jh * 4 + j4], al[i], bh[j4]);
                }
            }
        }
        __syncthreads();
        if (c + 2 < nc) load_chunk(c + 2, s);
    }

    // --------- epilogue ---------
    if (MODE == 2) {
        float* o0 = p.outF + (long long)z * p.oBatch;
        const int mB = bm + wm * 32 + (lane >> 2);
        const int nB = bn + wn * 64 + (lane & 3) * 2;
#pragma unroll
        for (int i = 0; i < 2; i++)
#pragma unroll
            for (int j = 0; j < 8; j++) {
                int m = mB + i * 16, n = nB + j * 8;
                *(float2*)(o0 + (long long)m * p.oRow + n)       = make_float2(acc[i][j][0], acc[i][j][1]);
                *(float2*)(o0 + (long long)(m + 8) * p.oRow + n) = make_float2(acc[i][j][2], acc[i][j][3]);
            }
    } else {
        const int sel = bn >> 9;                    // 0=Q 1=K 2=V
        if (sel < 2) {
            __half* o0 = sel ? p.kh : p.qh;
            __half* o1 = sel ? p.kl : p.ql;
            const int mB = bm + wm * 32 + (lane >> 2);
            const int nW = wn * 64 + (lane & 3) * 2;
#pragma unroll
            for (int i = 0; i < 2; i++)
#pragma unroll
                for (int j = 0; j < 8; j++) {
                    int m = mB + i * 16;
                    int nl = (bn & 511) + nW + j * 8;
                    float b0 = p.bias[bn + nW + j * 8], b1 = p.bias[bn + nW + j * 8 + 1];
                    unsigned short h0, l0, h1, l1;
#pragma unroll
                    for (int hf = 0; hf < 2; hf++) {
                        int mm = m + hf * 8;
                        split2h(acc[i][j][hf * 2 + 0] + b0, h0, l0);
                        split2h(acc[i][j][hf * 2 + 1] + b1, h1, l1);
                        long long a = (long long)mm * H_DIM + nl;
                        *(ushort2*)(o0 + a) = make_ushort2(h0, h1);
                        *(ushort2*)(o1 + a) = make_ushort2(l0, l1);
                    }
                }
        } else {
            // V: transposed single-fp16 out via smem staging, 2 phases of 128 cols
            uint32_t* stg = (uint32_t*)smem;        // [128][129]
            const int nloc0 = bn & 511;
#pragma unroll 1
            for (int phh = 0; phh < 2; phh++) {
                __syncthreads();
#pragma unroll
                for (int i = 0; i < 2; i++)
#pragma unroll
                    for (int jj = 0; jj < 4; jj++) {
                        int j = phh * 4 + jj;
#pragma unroll
                        for (int r = 0; r < 4; r++) {
                            int ml = wm * 32 + i * 16 + (r >> 1) * 8 + (lane >> 2);
                            int sc = wn * 32 + jj * 8 + (lane & 3) * 2 + (r & 1);
                            float v = acc[i][j][r] +
                                      p.bias[bn + wn * 64 + j * 8 + (lane & 3) * 2 + (r & 1)];
                            stg[ml * 129 + sc] = (uint32_t)__half_as_ushort(__float2half_rn(v));
                        }
                    }
                __syncthreads();
                int col = tid >> 2, rch = (tid & 3) * 32;
                int n = nloc0 + (col >> 5) * 64 + (col & 31) + phh * 32;
                long long base = (long long)n * NROWS + bm + rch;
#pragma unroll
                for (int r = 0; r < 32; r += 2) {
                    uint32_t w0 = stg[(rch + r) * 129 + col];
                    uint32_t w1 = stg[(rch + r + 1) * 129 + col];
                    *(ushort2*)(p.vt + base + r) =
                        make_ushort2((unsigned short)w0, (unsigned short)w1);
                }
            }
        }
    }
}

// ---------------- prep: pe table + stacked weight splits + stacked bias ------
__global__ void prep_kernel(const float* __restrict__ Wq, const float* __restrict__ Wk,
                            const float* __restrict__ Wv,
                            const float* __restrict__ bq, const float* __restrict__ bk,
                            const float* __restrict__ bv,
                            float* __restrict__ pe, float* __restrict__ bias,
                            __half* __restrict__ wh, __half* __restrict__ wl) {
    int b = blockIdx.x, t = threadIdx.x;
    if (b < 4096) {                                    // pe: 1M elements
        int idx = b * 256 + t;
        int h = idx & (H_DIM - 1);
        int s = idx >> 9;
        int j = (h < H_DIM / 2) ? h : h - H_DIM / 2;
        double d   = exp(-((double)(2 * j)) * (log(10000.0) / (double)H_DIM));
        double ang = (double)s * d;
        pe[idx] = (float)((h < H_DIM / 2) ? sin(ang) : cos(ang));
    } else if (b < 4096 + 3072) {                      // stacked weights 1536x512
        int idx = (b - 4096) * 256 + t;                // [0, 786432)
        int w = idx >> 18;                             // /262144
        int off = idx & 262143;
        const float* W = (w == 0) ? Wq : (w == 1) ? Wk : Wv;
        unsigned short h, l;
        split2h(W[off], h, l);
        wh[idx] = __ushort_as_half(h);
        wl[idx] = __ushort_as_half(l);
    } else {                                           // stacked bias 1536
        int i = (b - 4096 - 3072) * 256 + t;
        if (i < NSTACK)
            bias[i] = (i < 512) ? bq[i] : (i < 1024) ? bk[i - 512] : bv[i - 1024];
    }
}

__global__ void conv_x_kernel(const float* __restrict__ in, const float* __restrict__ pe,
                              __half* __restrict__ xh, __half* __restrict__ xl) {
    int i = blockIdx.x * blockDim.x + threadIdx.x;
    if (i >= NROWS * H_DIM) return;
    float v = in[i] + pe[i & (S_DIM * H_DIM - 1)];
    unsigned short h, l;
    split2h(v, h, l);
    xh[i] = __ushort_as_half(h);
    xl[i] = __ushort_as_half(l);
}

// ---------------- softmax: fp32 in, fp16 out, contiguous 8/thread -----------
__global__ __launch_bounds__(256) void softmax_kernel(const float* __restrict__ sc,
                                                      __half* __restrict__ ph) {
    const float* row = sc + (long long)blockIdx.x * S_DIM;
    long long obase = (long long)blockIdx.x * S_DIM + threadIdx.x * 8;
    int tid = threadIdx.x;
    __shared__ float red[256];

    float4 a = *(const float4*)(row + tid * 8);
    float4 b = *(const float4*)(row + tid * 8 + 4);
    float m = fmaxf(fmaxf(fmaxf(a.x, a.y), fmaxf(a.z, a.w)),
                    fmaxf(fmaxf(b.x, b.y), fmaxf(b.z, b.w)));
    red[tid] = m; __syncthreads();
    for (int s = 128; s > 0; s >>= 1) {
        if (tid < s) red[tid] = fmaxf(red[tid], red[tid + s]);
        __syncthreads();
    }
    m = red[0]; __syncthreads();

    float e[8];
    e[0] = expf(a.x - m); e[1] = expf(a.y - m); e[2] = expf(a.z - m); e[3] = expf(a.w - m);
    e[4] = expf(b.x - m); e[5] = expf(b.y - m); e[6] = expf(b.z - m); e[7] = expf(b.w - m);
    float sum = 0.f;
#pragma unroll
    for (int i = 0; i < 8; i++) sum += e[i];
    red[tid] = sum; __syncthreads();
    for (int s = 128; s > 0; s >>= 1) {
        if (tid < s) red[tid] += red[tid + s];
        __syncthreads();
    }
    float inv = 1.f / red[0];
#pragma unroll
    for (int i = 0; i < 4; i++) {
        __half2 w2 = __floats2half2_rn(e[i * 2] * inv, e[i * 2 + 1] * inv);
        *(__half2*)(ph + obase + i * 2) = w2;
    }
}

// ---------------- launch ----------------------------------------------------
extern "C" void kernel_launch(void* const* d_in, const int* in_sizes, int n_in,
                              void* d_out, int out_size) {
    const float* in_e = (const float*)d_in[0];
    const float* Wq   = (const float*)d_in[1];
    const float* bq   = (const float*)d_in[2];
    const float* Wk   = (const float*)d_in[3];
    const float* bk   = (const float*)d_in[4];
    const float* Wv   = (const float*)d_in[5];
    const float* bv   = (const float*)d_in[6];
    float* out = (float*)d_out;

    const int SMEM3 = 2 * (2 * TILE_A + 2 * TILE_B);   // 122880
    const int SMEM1 = 2 * (TILE_A + TILE_B);           // 61440
    cudaFuncSetAttribute(tc_gemm<3,0>, cudaFuncAttributeMaxDynamicSharedMemorySize, SMEM3);
    cudaFuncSetAttribute(tc_gemm<3,2>, cudaFuncAttributeMaxDynamicSharedMemorySize, SMEM3);
    cudaFuncSetAttribute(tc_gemm<1,2>, cudaFuncAttributeMaxDynamicSharedMemorySize, SMEM1);

#define SYM(v, s) void* v##_; cudaGetSymbolAddress(&v##_, s);
    SYM(pe, g_pe) SYM(bias, g_bias) SYM(xh, g_xh) SYM(xl, g_xl)
    SYM(wh, g_wh) SYM(wl, g_wl)
    SYM(qh, g_qh) SYM(ql, g_ql) SYM(kh, g_kh) SYM(kl, g_kl)
    SYM(vt, g_vt) SYM(sc, g_sc) SYM(sph, g_ph)
#undef SYM

    // 0: prep (pe + stacked weights + stacked bias)
    prep_kernel<<<4096 + 3072 + 6, 256>>>(Wq, Wk, Wv, bq, bk, bv,
        (float*)pe_, (float*)bias_, (__half*)wh_, (__half*)wl_);
    // 1: x = embeds + pe, split hi/lo
    conv_x_kernel<<<(NROWS * H_DIM + 255) / 256, 256>>>(in_e, (float*)pe_,
        (__half*)xh_, (__half*)xl_);

    GemmParams p;
    p.qh = (__half*)qh_; p.ql = (__half*)ql_;
    p.kh = (__half*)kh_; p.kl = (__half*)kl_;
    p.vt = (__half*)vt_;

    // 2: fused QKV: [16384,1536] = x @ Wstack^T + b
    p.Ah = (const __half*)xh_; p.Al = (const __half*)xl_;
    p.Bh = (const __half*)wh_; p.Bl = (const __half*)wl_;
    p.bias = (const float*)bias_;
    p.aBatch = 0; p.bBatch = 0; p.aRow = H_DIM; p.bRow = H_DIM; p.K = H_DIM;
    p.outF = nullptr; p.oBatch = 0; p.oRow = 0;
    dim3 gqkv(NSTACK / 256, NROWS / 128, 1);
    tc_gemm<3,0><<<gqkv, 512, SMEM3>>>(p);

    // 3: scores = q @ k^T per batch (fp32 out)
    p.Ah = (const __half*)qh_; p.Al = (const __half*)ql_;
    p.Bh = (const __half*)kh_; p.Bl = (const __half*)kl_;
    p.aBatch = (long long)S_DIM * H_DIM; p.bBatch = (long long)S_DIM * H_DIM;
    p.aRow = H_DIM; p.bRow = H_DIM; p.K = H_DIM;
    p.outF = (float*)sc_;
    p.oBatch = (long long)S_DIM * S_DIM; p.oRow = S_DIM;
    dim3 gs(S_DIM / 256, S_DIM / 128, B_DIM);
    tc_gemm<3,2><<<gs, 512, SMEM3>>>(p);

    // 4: softmax -> fp16 probs
    softmax_kernel<<<B_DIM * S_DIM, 256>>>((const float*)sc_, (__half*)sph_);

    // 5: out = probs @ v  (single product, NT with B = vT)
    p.Ah = (const __half*)sph_; p.Al = nullptr;
    p.Bh = (const __half*)vt_;  p.Bl = nullptr;
    p.aBatch = (long long)S_DIM * S_DIM; p.bBatch = S_DIM;
    p.aRow = S_DIM; p.bRow = NROWS; p.K = S_DIM;
    p.outF = out;
    p.oBatch = (long long)S_DIM * H_DIM; p.oRow = H_DIM;
    dim3 go(H_DIM / 256, S_DIM / 128, B_DIM);
    tc_gemm<1,2><<<go, 512, SMEM1>>>(p);
}

// round 8
// speedup vs baseline: 1.3895x; 1.3895x over previous
#include <cuda_runtime.h>
#include <cuda_fp16.h>
#include <cstdint>
#include <math.h>

#define B_DIM 8
#define S_DIM 2048
#define H_DIM 512
#define NROWS (B_DIM * S_DIM)          // 16384
#define NSTACK (3 * H_DIM)             // 1536

// ---------------- scratch (device globals; no allocations allowed) ----------
__device__ float g_pe[S_DIM * H_DIM];
__device__ float g_bias[NSTACK];
__device__ __half g_xh[NROWS * H_DIM], g_xl[NROWS * H_DIM];
__device__ __half g_wh[NSTACK * H_DIM], g_wl[NSTACK * H_DIM];   // stacked Wq,Wk,Wv
__device__ __half g_qh[NROWS * H_DIM], g_ql[NROWS * H_DIM];
__device__ __half g_kh[NROWS * H_DIM], g_kl[NROWS * H_DIM];
__device__ __half g_vt[H_DIM * NROWS];                          // v transposed, fp16
__device__ float g_sc[(long long)B_DIM * S_DIM * S_DIM];        // 134 MB
__device__ __half g_ph[(long long)B_DIM * S_DIM * S_DIM];       // probs fp16

// ---------------- helpers ----------------------------------------------
__device__ __forceinline__ uint32_t smem_u32(const void* p) {
    uint32_t a;
    asm("{ .reg .u64 t; cvta.to.shared.u64 t, %1; cvt.u32.u64 %0, t; }" : "=r"(a) : "l"(p));
    return a;
}
__device__ __forceinline__ void cp16(uint32_t dst, const void* src) {
    asm volatile("cp.async.cg.shared.global [%0], [%1], 16;"
                 :: "r"(dst), "l"(__cvta_generic_to_global(src)));
}
#define CP_COMMIT() asm volatile("cp.async.commit_group;" ::: "memory")
#define CP_WAIT_1() asm volatile("cp.async.wait_group 1;" ::: "memory")
#define CP_WAIT_0() asm volatile("cp.async.wait_group 0;" ::: "memory")

__device__ __forceinline__ void ldsm4(uint32_t& r0, uint32_t& r1, uint32_t& r2, uint32_t& r3,
                                      uint32_t addr) {
    asm volatile("ldmatrix.sync.aligned.m8n8.x4.shared.b16 {%0,%1,%2,%3}, [%4];"
                 : "=r"(r0), "=r"(r1), "=r"(r2), "=r"(r3) : "r"(addr));
}
__device__ __forceinline__ void mma16816(float* c, const uint32_t* a, const uint32_t* b) {
    asm volatile(
        "mma.sync.aligned.m16n8k16.row.col.f32.f16.f16.f32 "
        "{%0,%1,%2,%3}, {%4,%5,%6,%7}, {%8,%9}, {%0,%1,%2,%3};"
        : "+f"(c[0]), "+f"(c[1]), "+f"(c[2]), "+f"(c[3])
        : "r"(a[0]), "r"(a[1]), "r"(a[2]), "r"(a[3]), "r"(b[0]), "r"(b[1]));
}
__device__ __forceinline__ void split2h(float v, unsigned short& h, unsigned short& l) {
    __half hh = __float2half_rn(v);
    __half ll = __float2half_rn(v - __half2float(hh));
    h = __half_as_ushort(hh);
    l = __half_as_ushort(ll);
}

// ---------------- split-fp16 HMMA GEMM: C = A * B^T -------------------------
// Block tile 128x128, BK=32, 256 threads (4x2 warps), warp tile 32x64.
// SMEM rows: pitch 80B (64B data + 16B pad) -> conflict-free ldsm.
// NPROD=3: A hi/lo + B hi/lo (3-product). NPROD=1: single x single.
struct GemmParams {
    const __half *Ah, *Al, *Bh, *Bl;
    const float* bias;
    long long aBatch, bBatch;
    int aRow, bRow, K;
    __half *qh, *ql, *kh, *kl, *vt;    // MODE 0 outputs
    float* outF;                        // MODE 2 output
    long long oBatch;
    int oRow;
};

#define PITCH   80
#define TILE_SZ (128 * PITCH)           // 10240

template<int NPROD, int MODE>   // MODE: 0 = fused QKV epilogue, 2 = fp32 out
__global__ __launch_bounds__(256, 2) void tc_gemm(GemmParams p) {
    constexpr int NT = (NPROD == 3) ? 4 : 2;
    constexpr int STAGE = NT * TILE_SZ;
    extern __shared__ char smem[];
    uint32_t sbase = smem_u32(smem);

    const int tid = threadIdx.x;
    const int wid = tid >> 5, lane = tid & 31;
    const int wm = wid & 3, wn = wid >> 2;          // warp tile (wm*32, wn*64)

    const int bm = blockIdx.y * 128, bn = blockIdx.x * 128, z = blockIdx.z;
    const __half* Ah = p.Ah + (long long)z * p.aBatch;
    const __half* Al = p.Al + (long long)z * p.aBatch;
    const __half* Bh = p.Bh + (long long)z * p.bBatch;
    const __half* Bl = p.Bl + (long long)z * p.bBatch;
    const int aRow = p.aRow, bRow = p.bRow;

    const int nc = p.K >> 5;

    auto load_chunk = [&](int c, int s) {
        uint32_t st = sbase + s * STAGE;
        long long kofs = (long long)c * 32;
#pragma unroll
        for (int t = 0; t < NT; t++) {
            const __half* src;
            int rbase, rstride;
            if (NPROD == 3) {
                if (t == 0)      { src = Ah; rbase = bm; rstride = aRow; }
                else if (t == 1) { src = Al; rbase = bm; rstride = aRow; }
                else if (t == 2) { src = Bh; rbase = bn; rstride = bRow; }
                else             { src = Bl; rbase = bn; rstride = bRow; }
            } else {
                if (t == 0)      { src = Ah; rbase = bm; rstride = aRow; }
                else             { src = Bh; rbase = bn; rstride = bRow; }
            }
            uint32_t tb = st + t * TILE_SZ;
#pragma unroll
            for (int it = 0; it < 2; it++) {
                int u = tid + it * 256;            // 512 units per tile
                int row = u >> 2, ch = u & 3;
                cp16(tb + row * PITCH + ch * 16,
                     src + (long long)(rbase + row) * rstride + kofs + ch * 8);
            }
        }
        CP_COMMIT();
    };

    float acc[2][8][4];
#pragma unroll
    for (int i = 0; i < 2; i++)
#pragma unroll
        for (int j = 0; j < 8; j++)
#pragma unroll
            for (int r = 0; r < 4; r++) acc[i][j][r] = 0.f;

    load_chunk(0, 0);
    if (nc > 1) load_chunk(1, 1);

    for (int c = 0; c < nc; c++) {
        int s = c & 1;
        if (c == nc - 1) CP_WAIT_0(); else CP_WAIT_1();
        __syncthreads();

        uint32_t st = sbase + s * STAGE;
        uint32_t aHB = st, aLB = st + TILE_SZ;
        uint32_t bHB = st + (NT - 2) * TILE_SZ;
        uint32_t bLB = st + (NT - 1) * TILE_SZ;
        if (NPROD == 1) bHB = st + TILE_SZ;

#pragma unroll
        for (int ks = 0; ks < 2; ks++) {
            const int chcol = (ks * 2 + (lane >> 4)) * 16;
            uint32_t ah[2][4], al[2][4];
#pragma unroll
            for (int t = 0; t < 2; t++) {
                int row = wm * 32 + t * 16 + (lane & 15);
                uint32_t off = row * PITCH + chcol;
                ldsm4(ah[t][0], ah[t][1], ah[t][2], ah[t][3], aHB + off);
                if (NPROD == 3)
                    ldsm4(al[t][0], al[t][1], al[t][2], al[t][3], aLB + off);
            }
#pragma unroll
            for (int jh = 0; jh < 2; jh++) {
                uint32_t bh[4][2], bl[4][2];
#pragma unroll
                for (int jj = 0; jj < 2; jj++) {
                    int row = wn * 64 + (jh * 2 + jj) * 16 + (lane & 15);
                    uint32_t off = row * PITCH + chcol;
                    uint32_t r0, r1, r2, r3;
                    ldsm4(r0, r1, r2, r3, bHB + off);
                    bh[jj * 2][0] = r0; bh[jj * 2][1] = r2;
                    bh[jj * 2 + 1][0] = r1; bh[jj * 2 + 1][1] = r3;
                    if (NPROD == 3) {
                        ldsm4(r0, r1, r2, r3, bLB + off);
                        bl[jj * 2][0] = r0; bl[jj * 2][1] = r2;
                        bl[jj * 2 + 1][0] = r1; bl[jj * 2 + 1][1] = r3;
                    }
                }
#pragma unroll
                for (int i = 0; i < 2; i++)
#pragma unroll
                    for (int j4 = 0; j4 < 4; j4++)
                        mma16816(acc[i][jh * 4 + j4], ah[i], bh[j4]);
                if (NPROD == 3) {
#pragma unroll
                    for (int i = 0; i < 2; i++)
#pragma unroll
                        for (int j4 = 0; j4 < 4; j4++)
                            mma16816(acc[i][jh * 4 + j4], ah[i], bl[j4]);
#pragma unroll
                    for (int i = 0; i < 2; i++)
#pragma unroll
                        for (int j4 = 0; j4 < 4; j4++)
                            mma16816(acc[i][jh * 4 + j4], al[i], bh[j4]);
                }
            }
        }
        __syncthreads();
        if (c + 2 < nc) load_chunk(c + 2, s);
    }

    // --------- epilogue ---------
    if (MODE == 2) {
        float* o0 = p.outF + (long long)z * p.oBatch;
        const int mB = bm + wm * 32 + (lane >> 2);
        const int nB = bn + wn * 64 + (lane & 3) * 2;
#pragma unroll
        for (int i = 0; i < 2; i++)
#pragma unroll
            for (int j = 0; j < 8; j++) {
                int m = mB + i * 16, n = nB + j * 8;
                *(float2*)(o0 + (long long)m * p.oRow + n)       = make_float2(acc[i][j][0], acc[i][j][1]);
                *(float2*)(o0 + (long long)(m + 8) * p.oRow + n) = make_float2(acc[i][j][2], acc[i][j][3]);
            }
    } else {
        const int sel = bn >> 9;                    // 0=Q 1=K 2=V
        if (sel < 2) {
            __half* o0 = sel ? p.kh : p.qh;
            __half* o1 = sel ? p.kl : p.ql;
            const int mB = bm + wm * 32 + (lane >> 2);
            const int nW = wn * 64 + (lane & 3) * 2;
#pragma unroll
            for (int i = 0; i < 2; i++)
#pragma unroll
                for (int j = 0; j < 8; j++) {
                    int m = mB + i * 16;
                    int nl = (bn & 511) + nW + j * 8;
                    float b0 = p.bias[bn + nW + j * 8], b1 = p.bias[bn + nW + j * 8 + 1];
                    unsigned short h0, l0, h1, l1;
#pragma unroll
                    for (int hf = 0; hf < 2; hf++) {
                        int mm = m + hf * 8;
                        split2h(acc[i][j][hf * 2 + 0] + b0, h0, l0);
                        split2h(acc[i][j][hf * 2 + 1] + b1, h1, l1);
                        long long a = (long long)mm * H_DIM + nl;
                        *(ushort2*)(o0 + a) = make_ushort2(h0, h1);
                        *(ushort2*)(o1 + a) = make_ushort2(l0, l1);
                    }
                }
        } else {
            // V: transposed fp16 out via smem staging [128][129] u32
            uint32_t* stg = (uint32_t*)smem;
            __syncthreads();
#pragma unroll
            for (int i = 0; i < 2; i++)
#pragma unroll
                for (int j = 0; j < 8; j++)
#pragma unroll
                    for (int r = 0; r < 4; r++) {
                        int ml = wm * 32 + i * 16 + (r >> 1) * 8 + (lane >> 2);
                        int nl = wn * 64 + j * 8 + (lane & 3) * 2 + (r & 1);
                        float v = acc[i][j][r] + p.bias[bn + nl];
                        stg[ml * 129 + nl] = (uint32_t)__half_as_ushort(__float2half_rn(v));
                    }
            __syncthreads();
            int col = tid >> 1, rch = (tid & 1) * 64;
            int n = (bn & 511) + col;
            long long base = (long long)n * NROWS + bm + rch;
#pragma unroll
            for (int r = 0; r < 64; r += 2) {
                uint32_t w0 = stg[(rch + r) * 129 + col];
                uint32_t w1 = stg[(rch + r + 1) * 129 + col];
                *(ushort2*)(p.vt + base + r) =
                    make_ushort2((unsigned short)w0, (unsigned short)w1);
            }
        }
    }
}

// ---------------- prep: pe table + stacked weight splits + stacked bias ------
__global__ void prep_kernel(const float* __restrict__ Wq, const float* __restrict__ Wk,
                            const float* __restrict__ Wv,
                            const float* __restrict__ bq, const float* __restrict__ bk,
                            const float* __restrict__ bv,
                            float* __restrict__ pe, float* __restrict__ bias,
                            __half* __restrict__ wh, __half* __restrict__ wl) {
    int b = blockIdx.x, t = threadIdx.x;
    if (b < 4096) {                                    // pe: 1M elements
        int idx = b * 256 + t;
        int h = idx & (H_DIM - 1);
        int s = idx >> 9;
        int j = (h < H_DIM / 2) ? h : h - H_DIM / 2;
        double d   = exp(-((double)(2 * j)) * (log(10000.0) / (double)H_DIM));
        double ang = (double)s * d;
        pe[idx] = (float)((h < H_DIM / 2) ? sin(ang) : cos(ang));
    } else if (b < 4096 + 3072) {                      // stacked weights 1536x512
        int idx = (b - 4096) * 256 + t;
        int w = idx >> 18;
        int off = idx & 262143;
        const float* W = (w == 0) ? Wq : (w == 1) ? Wk : Wv;
        unsigned short h, l;
        split2h(W[off], h, l);
        wh[idx] = __ushort_as_half(h);
        wl[idx] = __ushort_as_half(l);
    } else {                                           // stacked bias 1536
        int i = (b - 4096 - 3072) * 256 + t;
        if (i < NSTACK)
            bias[i] = (i < 512) ? bq[i] : (i < 1024) ? bk[i - 512] : bv[i - 1024];
    }
}

__global__ void conv_x_kernel(const float* __restrict__ in, const float* __restrict__ pe,
                              __half* __restrict__ xh, __half* __restrict__ xl) {
    int i = blockIdx.x * blockDim.x + threadIdx.x;
    if (i >= NROWS * H_DIM) return;
    float v = in[i] + pe[i & (S_DIM * H_DIM - 1)];
    unsigned short h, l;
    split2h(v, h, l);
    xh[i] = __ushort_as_half(h);
    xl[i] = __ushort_as_half(l);
}

// ---------------- softmax: fp32 in, fp16 out ---------------------------------
__global__ __launch_bounds__(256) void softmax_kernel(const float* __restrict__ sc,
                                                      __half* __restrict__ ph) {
    const float* row = sc + (long long)blockIdx.x * S_DIM;
    long long obase = (long long)blockIdx.x * S_DIM + threadIdx.x * 8;
    int tid = threadIdx.x;
    __shared__ float red[256];

    float4 a = *(const float4*)(row + tid * 8);
    float4 b = *(const float4*)(row + tid * 8 + 4);
    float m = fmaxf(fmaxf(fmaxf(a.x, a.y), fmaxf(a.z, a.w)),
                    fmaxf(fmaxf(b.x, b.y), fmaxf(b.z, b.w)));
    red[tid] = m; __syncthreads();
    for (int s = 128; s > 0; s >>= 1) {
        if (tid < s) red[tid] = fmaxf(red[tid], red[tid + s]);
        __syncthreads();
    }
    m = red[0]; __syncthreads();

    float e[8];
    e[0] = expf(a.x - m); e[1] = expf(a.y - m); e[2] = expf(a.z - m); e[3] = expf(a.w - m);
    e[4] = expf(b.x - m); e[5] = expf(b.y - m); e[6] = expf(b.z - m); e[7] = expf(b.w - m);
    float sum = 0.f;
#pragma unroll
    for (int i = 0; i < 8; i++) sum += e[i];
    red[tid] = sum; __syncthreads();
    for (int s = 128; s > 0; s >>= 1) {
        if (tid < s) red[tid] += red[tid + s];
        __syncthreads();
    }
    float inv = 1.f / red[0];
#pragma unroll
    for (int i = 0; i < 4; i++) {
        __half2 w2 = __floats2half2_rn(e[i * 2] * inv, e[i * 2 + 1] * inv);
        *(__half2*)(ph + obase + i * 2) = w2;
    }
}

// ---------------- launch ----------------------------------------------------
extern "C" void kernel_launch(void* const* d_in, const int* in_sizes, int n_in,
                              void* d_out, int out_size) {
    const float* in_e = (const float*)d_in[0];
    const float* Wq   = (const float*)d_in[1];
    const float* bq   = (const float*)d_in[2];
    const float* Wk   = (const float*)d_in[3];
    const float* bk   = (const float*)d_in[4];
    const float* Wv   = (const float*)d_in[5];
    const float* bv   = (const float*)d_in[6];
    float* out = (float*)d_out;

    const int SMEM3 = 2 * 4 * TILE_SZ;   // 81920
    const int SMEM1 = 2 * 2 * TILE_SZ;   // 40960
    cudaFuncSetAttribute(tc_gemm<3,0>, cudaFuncAttributeMaxDynamicSharedMemorySize, SMEM3);
    cudaFuncSetAttribute(tc_gemm<3,2>, cudaFuncAttributeMaxDynamicSharedMemorySize, SMEM3);
    cudaFuncSetAttribute(tc_gemm<1,2>, cudaFuncAttributeMaxDynamicSharedMemorySize, SMEM1);

#define SYM(v, s) void* v##_; cudaGetSymbolAddress(&v##_, s);
    SYM(pe, g_pe) SYM(bias, g_bias) SYM(xh, g_xh) SYM(xl, g_xl)
    SYM(wh, g_wh) SYM(wl, g_wl)
    SYM(qh, g_qh) SYM(ql, g_ql) SYM(kh, g_kh) SYM(kl, g_kl)
    SYM(vt, g_vt) SYM(sc, g_sc) SYM(sph, g_ph)
#undef SYM

    // 0: prep
    prep_kernel<<<4096 + 3072 + 6, 256>>>(Wq, Wk, Wv, bq, bk, bv,
        (float*)pe_, (float*)bias_, (__half*)wh_, (__half*)wl_);
    // 1: conv_x
    conv_x_kernel<<<(NROWS * H_DIM + 255) / 256, 256>>>(in_e, (float*)pe_,
        (__half*)xh_, (__half*)xl_);

    GemmParams p;
    p.qh = (__half*)qh_; p.ql = (__half*)ql_;
    p.kh = (__half*)kh_; p.kl = (__half*)kl_;
    p.vt = (__half*)vt_;

    // 2: fused QKV: [16384,1536] = x @ Wstack^T + b
    p.Ah = (const __half*)xh_; p.Al = (const __half*)xl_;
    p.Bh = (const __half*)wh_; p.Bl = (const __half*)wl_;
    p.bias = (const float*)bias_;
    p.aBatch = 0; p.bBatch = 0; p.aRow = H_DIM; p.bRow = H_DIM; p.K = H_DIM;
    p.outF = nullptr; p.oBatch = 0; p.oRow = 0;
    dim3 gqkv(NSTACK / 128, NROWS / 128, 1);
    tc_gemm<3,0><<<gqkv, 256, SMEM3>>>(p);

    // 3: scores = q @ k^T per batch (fp32 out)
    p.Ah = (const __half*)qh_; p.Al = (const __half*)ql_;
    p.Bh = (const __half*)kh_; p.Bl = (const __half*)kl_;
    p.aBatch = (long long)S_DIM * H_DIM; p.bBatch = (long long)S_DIM * H_DIM;
    p.aRow = H_DIM; p.bRow = H_DIM; p.K = H_DIM;
    p.outF = (float*)sc_;
    p.oBatch = (long long)S_DIM * S_DIM; p.oRow = S_DIM;
    dim3 gs(S_DIM / 128, S_DIM / 128, B_DIM);
    tc_gemm<3,2><<<gs, 256, SMEM3>>>(p);

    // 4: softmax -> fp16 probs
    softmax_kernel<<<B_DIM * S_DIM, 256>>>((const float*)sc_, (__half*)sph_);

    // 5: out = probs @ v (single product, NT with B = vT) — ncu -s 5 target
    p.Ah = (const __half*)sph_; p.Al = nullptr;
    p.Bh = (const __half*)vt_;  p.Bl = nullptr;
    p.aBatch = (long long)S_DIM * S_DIM; p.bBatch = S_DIM;
    p.aRow = S_DIM; p.bRow = NROWS; p.K = S_DIM;
    p.outF = out;
    p.oBatch = (long long)S_DIM * H_DIM; p.oRow = H_DIM;
    dim3 go(H_DIM / 128, S_DIM / 128, B_DIM);
    tc_gemm<1,2><<<go, 256, SMEM1>>>(p);
}